// round 15
// baseline (speedup 1.0000x reference)
#include <cuda_runtime.h>
#include <cstddef>
#include <cstdint>

#define NB 4
#define NN 512
#define NE 512
#define NH 32
#define ND 16
#define NP 128
#define CW 1088          // scratch C width: [q 512 | k 512 | w 32 | pad 32]
#define JT 128
#define NTILE (NN / JT)  // 4

// ---------------- device scratch ----------------
__device__ float g_xn[NB * NN * NE];
__device__ float g_Wcat[CW * NE];
__device__ float g_C[NB * NN * CW];
__device__ float g_wbg2[NP * NH];           // Wb*pln_g, pair-interleaved [p/2][h][2]
__device__ float g_c1[NH];
__device__ float g_c2[NH];
__device__ float g_qkm[(size_t)NB * NN * NH * NN];  // qk+mask [b,i][h][j], 134 MB
__device__ float g_wJ[NB * NN * NH];        // w j-major [token][h], 256 KB (L2 resident)
__device__ float g_qT[(size_t)NB * NH * NN * ND];   // q dense [b][h][i][d], 4 MB
__device__ float g_kT[(size_t)NB * NH * NN * ND];   // k dense [b][h][j][d], 4 MB

__device__ __forceinline__ void ffma2(unsigned long long& d, unsigned long long a, unsigned long long b) {
    asm("fma.rn.f32x2 %0, %1, %2, %0;" : "+l"(d) : "l"(a), "l"(b));
}
__device__ __forceinline__ void unpack2(float& lo, float& hi, unsigned long long v) {
    asm("mov.b64 {%0, %1}, %2;" : "=f"(lo), "=f"(hi) : "l"(v));
}

// ---------------- prep + layernorm combined ----------------
__global__ __launch_bounds__(256) void prep_ln_kernel(
    const float* __restrict__ Wq, const float* __restrict__ Wk,
    const float* __restrict__ Wv, const float* __restrict__ Wf,
    const float* __restrict__ Wb, const float* __restrict__ bb,
    const float* __restrict__ pg, const float* __restrict__ pb,
    const float* __restrict__ query, const float* __restrict__ ln_g,
    const float* __restrict__ ln_b)
{
    int r = blockIdx.x;
    int tid = threadIdx.x;
    if (r < 512) {
        for (int e = tid; e < NE; e += 256)
            g_Wcat[r * NE + e] = Wq[r * NE + e] * 0.25f;   // SCALING folded in
        return;
    } else if (r < 1024) {
        int rr = r - 512;
        for (int e = tid; e < NE; e += 256)
            g_Wcat[r * NE + e] = Wk[rr * NE + e];
        return;
    } else if (r < 1056) {
        int h = r - 1024;
        for (int e = tid; e < NE; e += 256) {
            float s = 0.f;
#pragma unroll
            for (int d = 0; d < ND; d++)
                s += Wf[h * ND + d] * Wv[(h * ND + d) * NE + e];
            g_Wcat[r * NE + e] = s;                        // Wvf
        }
        return;
    } else if (r < 1088) {
        for (int e = tid; e < NE; e += 256) g_Wcat[r * NE + e] = 0.f;
        return;
    } else if (r == 1088) {
        for (int t = tid; t < NP * NH; t += 256) {
            int p = t >> 5, h = t & 31;
            g_wbg2[(p >> 1) * 64 + h * 2 + (p & 1)] = Wb[h * NP + p] * pg[p];
        }
        return;
    } else if (r == 1089) {
        if (tid < NH) {
            int h = tid;
            float s1 = 0.f, s2 = 0.f;
            for (int p = 0; p < NP; p++) {
                float wv = Wb[h * NP + p];
                s1 += wv * pg[p];
                s2 += wv * pb[p];
            }
            g_c1[h] = s1;
            g_c2[h] = s2 + bb[h];
        }
        return;
    }
    // ---- LN row ----
    int row = r - 1090;
    const float* x = query + (size_t)row * NE;
    float2 v = *(const float2*)(x + tid * 2);
    float s  = v.x + v.y;
    float ss = v.x * v.x + v.y * v.y;
#pragma unroll
    for (int o = 16; o; o >>= 1) {
        s  += __shfl_xor_sync(0xffffffffu, s, o);
        ss += __shfl_xor_sync(0xffffffffu, ss, o);
    }
    __shared__ float rs[8], rss[8];
    int w = tid >> 5;
    if ((tid & 31) == 0) { rs[w] = s; rss[w] = ss; }
    __syncthreads();
    s = 0.f; ss = 0.f;
#pragma unroll
    for (int k = 0; k < 8; k++) { s += rs[k]; ss += rss[k]; }
    float mu   = s * (1.f / 512.f);
    float var  = ss * (1.f / 512.f) - mu * mu;
    float rstd = rsqrtf(var + 1e-5f);
    float2 gg = *(const float2*)(ln_g + tid * 2);
    float2 bv = *(const float2*)(ln_b + tid * 2);
    float2 o;
    o.x = (v.x - mu) * rstd * gg.x + bv.x;
    o.y = (v.y - mu) * rstd * gg.y + bv.y;
    *(float2*)(g_xn + (size_t)row * NE + tid * 2) = o;
}

// ---------------- GEMM: C[2048][1088] = xn @ Wcat^T (+ wJ/qT/kT side writes) ----------------
__global__ __launch_bounds__(256) void gemm_qkw_kernel()
{
    __shared__ float As[16][68];
    __shared__ float Bs[16][68];
    int m0 = blockIdx.x * 64, n0 = blockIdx.y * 64;
    int tid = threadIdx.x;
    int tm = tid >> 4, tn = tid & 15;
    int lr = tid >> 2, lc = tid & 3;
    float acc[4][4] = {};
    for (int k0 = 0; k0 < NE; k0 += 16) {
        float4 av = *(const float4*)&g_xn[(size_t)(m0 + lr) * NE + k0 + lc * 4];
        float4 bv = *(const float4*)&g_Wcat[(size_t)(n0 + lr) * NE + k0 + lc * 4];
        As[lc * 4 + 0][lr] = av.x; As[lc * 4 + 1][lr] = av.y;
        As[lc * 4 + 2][lr] = av.z; As[lc * 4 + 3][lr] = av.w;
        Bs[lc * 4 + 0][lr] = bv.x; Bs[lc * 4 + 1][lr] = bv.y;
        Bs[lc * 4 + 2][lr] = bv.z; Bs[lc * 4 + 3][lr] = bv.w;
        __syncthreads();
#pragma unroll
        for (int k = 0; k < 16; k++) {
            float4 a = *(const float4*)&As[k][tm * 4];
            float4 b = *(const float4*)&Bs[k][tn * 4];
            acc[0][0] += a.x * b.x; acc[0][1] += a.x * b.y; acc[0][2] += a.x * b.z; acc[0][3] += a.x * b.w;
            acc[1][0] += a.y * b.x; acc[1][1] += a.y * b.y; acc[1][2] += a.y * b.z; acc[1][3] += a.y * b.w;
            acc[2][0] += a.z * b.x; acc[2][1] += a.z * b.y; acc[2][2] += a.z * b.z; acc[2][3] += a.z * b.w;
            acc[3][0] += a.w * b.x; acc[3][1] += a.w * b.y; acc[3][2] += a.w * b.z; acc[3][3] += a.w * b.w;
        }
        __syncthreads();
    }
#pragma unroll
    for (int t = 0; t < 4; t++)
#pragma unroll
        for (int u = 0; u < 4; u++) {
            int m = m0 + tm * 4 + t, n = n0 + tn * 4 + u;
            float v = acc[t][u];
            g_C[(size_t)m * CW + n] = v;
            int b = m >> 9, tok = m & 511;
            if (n < 512) {
                int h = n >> 4, d = n & 15;
                g_qT[(((size_t)(b * NH + h)) * NN + tok) * ND + d] = v;
            } else if (n < 1024) {
                int nn = n - 512;
                int h = nn >> 4, d = nn & 15;
                g_kT[(((size_t)(b * NH + h)) * NN + tok) * ND + d] = v;
            } else if (n < 1056) {
                g_wJ[(size_t)m * NH + (n - 1024)] = v;
            }
        }
}

// ---------------- qk+mask kernel: coalesced q/k from g_qT/g_kT ----------------
__global__ __launch_bounds__(512) void qk_kernel(const float* __restrict__ mask)
{
    __shared__ float qs[128 * ND];   // 8 KB
    int ic = blockIdx.x, h = blockIdx.y, b = blockIdx.z;
    int tid = threadIdx.x;
    int j = tid;
    int i0 = ic * 128;

    {   // q tile: 128 rows x 16 d = 512 float4, fully contiguous
        const float4* qsrc = (const float4*)(g_qT + (((size_t)(b * NH + h)) * NN + i0) * ND);
        ((float4*)qs)[tid] = qsrc[tid];
    }
    const float* kr = g_kT + (((size_t)(b * NH + h)) * NN + j) * ND;
    float4 k0 = *(const float4*)(kr + 0);
    float4 k1 = *(const float4*)(kr + 4);
    float4 k2 = *(const float4*)(kr + 8);
    float4 k3 = *(const float4*)(kr + 12);
    __syncthreads();

    const float* mrow = mask + (((size_t)(b * NH + h) * NN + i0)) * NN + j;
    float* orow = g_qkm + ((size_t)(b * NN + i0) * NH + h) * NN + j;
#pragma unroll 1
    for (int ii = 0; ii < 128; ii += 8) {
        float mk[8];
#pragma unroll
        for (int t = 0; t < 8; t++) mk[t] = mrow[(size_t)(ii + t) * NN];
        float dv[8];
#pragma unroll
        for (int t = 0; t < 8; t++) {
            const float* q = &qs[(ii + t) * ND];
            float4 q0 = *(const float4*)(q + 0);
            float4 q1 = *(const float4*)(q + 4);
            float4 q2 = *(const float4*)(q + 8);
            float4 q3 = *(const float4*)(q + 12);
            dv[t] =
                q0.x * k0.x + q0.y * k0.y + q0.z * k0.z + q0.w * k0.w +
                q1.x * k1.x + q1.y * k1.y + q1.z * k1.z + q1.w * k1.w +
                q2.x * k2.x + q2.y * k2.y + q2.z * k2.z + q2.w * k2.w +
                q3.x * k3.x + q3.y * k3.y + q3.z * k3.z + q3.w * k3.w;
        }
#pragma unroll
        for (int t = 0; t < 8; t++)
            orow[(size_t)(ii + t) * NH * NN] = dv[t] + mk[t];
    }
}

// ---------------- fused attention kernel v13: stats fused into staging (no conflicted LDS) ----------------
// Warp = 4 jg x 8 hg. Warp stages its own 32-row pair window.
// smem floats: pair [128][132]=16896 | wbg2 4096 | mrg 4*32*5=640 => 21632 (86.5 KB)
#define WBG_BASE  16896
#define MRG_BASE  (16896 + 4096)
#define SM_FLOATS (16896 + 4096 + 640)

__global__ __launch_bounds__(128, 2) void fused_attn_kernel(
    const float* __restrict__ pair, const float* __restrict__ dpos,
    float* __restrict__ out)
{
    extern __shared__ float sm[];
    float* pair_s = sm;

    int bi = blockIdx.x;                       // b*512 + i
    int b = bi >> 9;
    int tid = threadIdx.x;
    int lane = tid & 31, w = tid >> 5;         // 4 warps
    int hg = tid & 7, hg4 = hg * 4;
    int jg = tid >> 3;                         // 0..15
    int jl0 = jg * 8;                          // local row base (8 rows per thread)
    int mygrp = lane >> 3;                     // batch index whose rows this thread owns

    // one-time: wbg to smem, per-head constants to regs
    for (int t = tid; t < 1024; t += 128)
        ((float4*)(sm + WBG_BASE))[t] = ((const float4*)g_wbg2)[t];
    float4 c1v = *(const float4*)&g_c1[hg4];
    float4 c2v = *(const float4*)&g_c2[hg4];
    float c1a[4] = { c1v.x, c1v.y, c1v.z, c1v.w };
    float c2a[4] = { c2v.x, c2v.y, c2v.z, c2v.w };
    __syncthreads();

    const float* pbase = pair + (size_t)bi * NN * NP;
    const float* lbase = g_qkm + (size_t)bi * NH * NN;
    const unsigned long long* wb = (const unsigned long long*)(sm + WBG_BASE);

    // flash state per owned head u
    float m_r[4] = { -1e30f, -1e30f, -1e30f, -1e30f };
    float z_r[4] = { 0.f, 0.f, 0.f, 0.f };
    float a0_r[4] = {}, a1_r[4] = {}, a2_r[4] = {};

    for (int tile = 0; tile < NTILE; ++tile) {
        int j0 = tile * JT;

        // ---- warp-private staging: 32 rows, coalesced; LN stats from the staged regs ----
        float muv[8], rsv[8];
        {
            const float* psrc = pbase + (size_t)(j0 + w * 32) * NP + lane * 4;
#pragma unroll
            for (int batch = 0; batch < 4; ++batch) {
                float4 ld[8];
#pragma unroll
                for (int it = 0; it < 8; ++it)
                    ld[it] = *(const float4*)(psrc + (size_t)(batch * 8 + it) * NP);
#pragma unroll
                for (int it = 0; it < 8; ++it)
                    *(float4*)&pair_s[(w * 32 + batch * 8 + it) * 132 + lane * 4] = ld[it];
                // per-row partial sums over this lane's 4 columns
                float s8[8], q8[8];
#pragma unroll
                for (int it = 0; it < 8; ++it) {
                    float4 v = ld[it];
                    s8[it] = v.x + v.y + v.z + v.w;
                    q8[it] = v.x * v.x + v.y * v.y + v.z * v.z + v.w * v.w;
                }
                // butterfly: every lane ends with full row sums for the 8 batch rows
#pragma unroll
                for (int off = 16; off; off >>= 1) {
#pragma unroll
                    for (int it = 0; it < 8; ++it) {
                        s8[it] += __shfl_xor_sync(0xffffffffu, s8[it], off);
                        q8[it] += __shfl_xor_sync(0xffffffffu, q8[it], off);
                    }
                }
                if (mygrp == batch) {
#pragma unroll
                    for (int t = 0; t < 8; ++t) {
                        float mu  = s8[t] * (1.f / 128.f);
                        float var = q8[t] * (1.f / 128.f) - mu * mu;
                        muv[t] = mu;
                        rsv[t] = rsqrtf(var + 1e-5f);
                    }
                }
            }
        }
        __syncwarp();

        // ---- bias GEMM in f32x2: 8j x 4h, K=128 as 32 p4-chunks ----
        unsigned long long acc2[8][4] = {};
        const ulonglong2* pab = (const ulonglong2*)&pair_s[jl0 * 132];  // row stride = 33 ulonglong2
#pragma unroll 4
        for (int p4 = 0; p4 < 32; ++p4) {
            ulonglong2 a[8];
#pragma unroll
            for (int t = 0; t < 8; t++) a[t] = pab[t * 33 + p4];
            int p2 = p4 * 2;
            ulonglong2 wA0 = *(const ulonglong2*)&wb[(size_t)(p2 + 0) * 32 + hg4];
            ulonglong2 wB0 = *(const ulonglong2*)&wb[(size_t)(p2 + 0) * 32 + hg4 + 2];
            ulonglong2 wA1 = *(const ulonglong2*)&wb[(size_t)(p2 + 1) * 32 + hg4];
            ulonglong2 wB1 = *(const ulonglong2*)&wb[(size_t)(p2 + 1) * 32 + hg4 + 2];
#pragma unroll
            for (int t = 0; t < 8; t++) {
                ffma2(acc2[t][0], a[t].x, wA0.x); ffma2(acc2[t][1], a[t].x, wA0.y);
                ffma2(acc2[t][2], a[t].x, wB0.x); ffma2(acc2[t][3], a[t].x, wB0.y);
                ffma2(acc2[t][0], a[t].y, wA1.x); ffma2(acc2[t][1], a[t].y, wA1.y);
                ffma2(acc2[t][2], a[t].y, wB1.x); ffma2(acc2[t][3], a[t].y, wB1.y);
            }
        }

        // ---- epilogue: qkm (2x float4 per head), w j-major, dpos; online softmax ----
        float qk[4][8];
#pragma unroll
        for (int u = 0; u < 4; u++) {
            const float* qr = lbase + (size_t)(hg4 + u) * NN + j0 + jl0;
            float4 qa = *(const float4*)qr;
            float4 qb = *(const float4*)(qr + 4);
            qk[u][0] = qa.x; qk[u][1] = qa.y; qk[u][2] = qa.z; qk[u][3] = qa.w;
            qk[u][4] = qb.x; qk[u][5] = qb.y; qk[u][6] = qb.z; qk[u][7] = qb.w;
        }
#pragma unroll
        for (int t = 0; t < 8; t++) {
            int j = j0 + jl0 + t;
            float4 w4 = *(const float4*)(g_wJ + (size_t)(b * NN + j) * NH + hg4);
            const float* dp = dpos + ((size_t)bi * NN + j) * 3;
            float dp0 = dp[0], dp1 = dp[1], dp2 = dp[2];
            float accf[4];
            float lo, hi;
            unpack2(lo, hi, acc2[t][0]); accf[0] = lo + hi;
            unpack2(lo, hi, acc2[t][1]); accf[1] = lo + hi;
            unpack2(lo, hi, acc2[t][2]); accf[2] = lo + hi;
            unpack2(lo, hi, acc2[t][3]); accf[3] = lo + hi;
            float wr[4] = { w4.x, w4.y, w4.z, w4.w };
#pragma unroll
            for (int u = 0; u < 4; u++) {
                float lv = rsv[t] * (accf[u] - muv[t] * c1a[u]) + c2a[u] + qk[u][t];
                float nm = fmaxf(m_r[u], lv);
                float sc = __expf(m_r[u] - nm);
                float e  = __expf(lv - nm);
                m_r[u] = nm;
                z_r[u] = z_r[u] * sc + e;
                float ew = e * wr[u];
                a0_r[u] = a0_r[u] * sc + ew * dp0;
                a1_r[u] = a1_r[u] * sc + ew * dp1;
                a2_r[u] = a2_r[u] * sc + ew * dp2;
            }
        }
        __syncwarp();   // next tile staging must not overwrite rows still being read
    }

    // ---- flash merge: shfl over 4 jg sharing hg (xor 8,16), then across 4 warps ----
#pragma unroll
    for (int u = 0; u < 4; u++) {
#pragma unroll
        for (int off = 8; off <= 16; off <<= 1) {
            float om = __shfl_xor_sync(0xffffffffu, m_r[u], off);
            float oz = __shfl_xor_sync(0xffffffffu, z_r[u], off);
            float o0 = __shfl_xor_sync(0xffffffffu, a0_r[u], off);
            float o1 = __shfl_xor_sync(0xffffffffu, a1_r[u], off);
            float o2 = __shfl_xor_sync(0xffffffffu, a2_r[u], off);
            float M = fmaxf(m_r[u], om);
            float s1 = __expf(m_r[u] - M);
            float s2 = __expf(om - M);
            z_r[u]  = z_r[u]  * s1 + oz * s2;
            a0_r[u] = a0_r[u] * s1 + o0 * s2;
            a1_r[u] = a1_r[u] * s1 + o1 * s2;
            a2_r[u] = a2_r[u] * s1 + o2 * s2;
            m_r[u] = M;
        }
    }
    __syncthreads();
    float* mrg = sm + MRG_BASE;
    if (lane < 8) {
#pragma unroll
        for (int u = 0; u < 4; u++) {
            int h = lane * 4 + u;
            float* e = &mrg[(w * 32 + h) * 5];
            e[0] = m_r[u]; e[1] = z_r[u]; e[2] = a0_r[u]; e[3] = a1_r[u]; e[4] = a2_r[u];
        }
    }
    __syncthreads();
    if (tid < 32) {
        int h = tid;
        float M = -1e30f, Z = 0.f, A0 = 0.f, A1 = 0.f, A2 = 0.f;
#pragma unroll
        for (int ww = 0; ww < 4; ww++) {
            const float* e = &mrg[(ww * 32 + h) * 5];
            float om = e[0];
            float nM = fmaxf(M, om);
            float s1 = __expf(M - nM);
            float s2 = __expf(om - nM);
            Z  = Z * s1 + e[1] * s2;
            A0 = A0 * s1 + e[2] * s2;
            A1 = A1 * s1 + e[3] * s2;
            A2 = A2 * s1 + e[4] * s2;
            M = nM;
        }
        float inv = 1.f / Z;
        float f0 = A0 * inv, f1 = A1 * inv, f2 = A2 * inv;
#pragma unroll
        for (int o = 16; o; o >>= 1) {
            f0 += __shfl_xor_sync(0xffffffffu, f0, o);
            f1 += __shfl_xor_sync(0xffffffffu, f1, o);
            f2 += __shfl_xor_sync(0xffffffffu, f2, o);
        }
        if (tid == 0) {
            out[(size_t)bi * 3 + 0] = f0;
            out[(size_t)bi * 3 + 1] = f1;
            out[(size_t)bi * 3 + 2] = f2;
        }
    }
}

// ---------------- launcher ----------------
extern "C" void kernel_launch(void* const* d_in, const int* in_sizes, int n_in,
                              void* d_out, int out_size)
{
    (void)in_sizes; (void)n_in; (void)out_size;
    const float* query  = (const float*)d_in[0];
    const float* pair   = (const float*)d_in[1];
    const float* mask   = (const float*)d_in[2];
    const float* dpos   = (const float*)d_in[3];
    const float* ln_g   = (const float*)d_in[4];
    const float* ln_b   = (const float*)d_in[5];
    const float* Wq     = (const float*)d_in[6];
    const float* Wk     = (const float*)d_in[7];
    const float* Wv     = (const float*)d_in[8];
    const float* pln_g  = (const float*)d_in[9];
    const float* pln_b  = (const float*)d_in[10];
    const float* Wb     = (const float*)d_in[11];
    const float* bb     = (const float*)d_in[12];
    const float* Wf     = (const float*)d_in[13];
    float* out = (float*)d_out;

    static_assert(SM_FLOATS * 4 <= 113 * 1024, "smem budget for 2 CTAs/SM");
    cudaFuncSetAttribute(fused_attn_kernel,
                         cudaFuncAttributeMaxDynamicSharedMemorySize, SM_FLOATS * 4);

    prep_ln_kernel<<<1090 + NB * NN, 256>>>(Wq, Wk, Wv, Wf, Wb, bb, pln_g, pln_b,
                                            query, ln_g, ln_b);
    gemm_qkw_kernel<<<dim3(32, 17), 256>>>();
    qk_kernel<<<dim3(4, NH, NB), 512>>>(mask);
    fused_attn_kernel<<<NB * NN, 128, SM_FLOATS * 4>>>(pair, dpos, out);
}

// round 17
// speedup vs baseline: 1.1480x; 1.1480x over previous
#include <cuda_runtime.h>
#include <cstddef>
#include <cstdint>

#define NB 4
#define NN 512
#define NE 512
#define NH 32
#define ND 16
#define NP 128
#define CW 1088          // scratch C width: [q 512 | k 512 | w 32 | pad 32]
#define JT 128
#define NTILE (NN / JT)  // 4

// ---------------- device scratch ----------------
__device__ float g_xn[NB * NN * NE];
__device__ float g_Wcat[CW * NE];
__device__ float g_C[NB * NN * CW];
__device__ float g_wbg2[NP * NH];           // Wb*pln_g, pair-interleaved [p/2][h][2]
__device__ float g_c1[NH];
__device__ float g_c2[NH];
__device__ float g_qkm[(size_t)NB * NN * NH * NN];  // qk+mask [b,i][h][j], 134 MB
__device__ float g_wJ[NB * NN * NH];        // w j-major [token][h], 256 KB (L2 resident)

__device__ __forceinline__ void ffma2(unsigned long long& d, unsigned long long a, unsigned long long b) {
    asm("fma.rn.f32x2 %0, %1, %2, %0;" : "+l"(d) : "l"(a), "l"(b));
}
__device__ __forceinline__ void unpack2(float& lo, float& hi, unsigned long long v) {
    asm("mov.b64 {%0, %1}, %2;" : "=f"(lo), "=f"(hi) : "l"(v));
}

// ---------------- prep + layernorm combined ----------------
__global__ __launch_bounds__(256) void prep_ln_kernel(
    const float* __restrict__ Wq, const float* __restrict__ Wk,
    const float* __restrict__ Wv, const float* __restrict__ Wf,
    const float* __restrict__ Wb, const float* __restrict__ bb,
    const float* __restrict__ pg, const float* __restrict__ pb,
    const float* __restrict__ query, const float* __restrict__ ln_g,
    const float* __restrict__ ln_b)
{
    int r = blockIdx.x;
    int tid = threadIdx.x;
    if (r < 512) {
        for (int e = tid; e < NE; e += 256)
            g_Wcat[r * NE + e] = Wq[r * NE + e] * 0.25f;   // SCALING folded in
        return;
    } else if (r < 1024) {
        int rr = r - 512;
        for (int e = tid; e < NE; e += 256)
            g_Wcat[r * NE + e] = Wk[rr * NE + e];
        return;
    } else if (r < 1056) {
        int h = r - 1024;
        for (int e = tid; e < NE; e += 256) {
            float s = 0.f;
#pragma unroll
            for (int d = 0; d < ND; d++)
                s += Wf[h * ND + d] * Wv[(h * ND + d) * NE + e];
            g_Wcat[r * NE + e] = s;                        // Wvf
        }
        return;
    } else if (r < 1088) {
        for (int e = tid; e < NE; e += 256) g_Wcat[r * NE + e] = 0.f;
        return;
    } else if (r == 1088) {
        for (int t = tid; t < NP * NH; t += 256) {
            int p = t >> 5, h = t & 31;
            g_wbg2[(p >> 1) * 64 + h * 2 + (p & 1)] = Wb[h * NP + p] * pg[p];
        }
        return;
    } else if (r == 1089) {
        if (tid < NH) {
            int h = tid;
            float s1 = 0.f, s2 = 0.f;
            for (int p = 0; p < NP; p++) {
                float wv = Wb[h * NP + p];
                s1 += wv * pg[p];
                s2 += wv * pb[p];
            }
            g_c1[h] = s1;
            g_c2[h] = s2 + bb[h];
        }
        return;
    }
    // ---- LN row ----
    int row = r - 1090;
    const float* x = query + (size_t)row * NE;
    float2 v = *(const float2*)(x + tid * 2);
    float s  = v.x + v.y;
    float ss = v.x * v.x + v.y * v.y;
#pragma unroll
    for (int o = 16; o; o >>= 1) {
        s  += __shfl_xor_sync(0xffffffffu, s, o);
        ss += __shfl_xor_sync(0xffffffffu, ss, o);
    }
    __shared__ float rs[8], rss[8];
    int w = tid >> 5;
    if ((tid & 31) == 0) { rs[w] = s; rss[w] = ss; }
    __syncthreads();
    s = 0.f; ss = 0.f;
#pragma unroll
    for (int k = 0; k < 8; k++) { s += rs[k]; ss += rss[k]; }
    float mu   = s * (1.f / 512.f);
    float var  = ss * (1.f / 512.f) - mu * mu;
    float rstd = rsqrtf(var + 1e-5f);
    float2 gg = *(const float2*)(ln_g + tid * 2);
    float2 bv = *(const float2*)(ln_b + tid * 2);
    float2 o;
    o.x = (v.x - mu) * rstd * gg.x + bv.x;
    o.y = (v.y - mu) * rstd * gg.y + bv.y;
    *(float2*)(g_xn + (size_t)row * NE + tid * 2) = o;
}

// ---------------- GEMM: C[2048][1088] = xn @ Wcat^T (+ g_wJ side write) ----------------
__global__ __launch_bounds__(256) void gemm_qkw_kernel()
{
    __shared__ float As[16][68];
    __shared__ float Bs[16][68];
    int m0 = blockIdx.x * 64, n0 = blockIdx.y * 64;
    int tid = threadIdx.x;
    int tm = tid >> 4, tn = tid & 15;
    int lr = tid >> 2, lc = tid & 3;
    float acc[4][4] = {};
    for (int k0 = 0; k0 < NE; k0 += 16) {
        float4 av = *(const float4*)&g_xn[(size_t)(m0 + lr) * NE + k0 + lc * 4];
        float4 bv = *(const float4*)&g_Wcat[(size_t)(n0 + lr) * NE + k0 + lc * 4];
        As[lc * 4 + 0][lr] = av.x; As[lc * 4 + 1][lr] = av.y;
        As[lc * 4 + 2][lr] = av.z; As[lc * 4 + 3][lr] = av.w;
        Bs[lc * 4 + 0][lr] = bv.x; Bs[lc * 4 + 1][lr] = bv.y;
        Bs[lc * 4 + 2][lr] = bv.z; Bs[lc * 4 + 3][lr] = bv.w;
        __syncthreads();
#pragma unroll
        for (int k = 0; k < 16; k++) {
            float4 a = *(const float4*)&As[k][tm * 4];
            float4 b = *(const float4*)&Bs[k][tn * 4];
            acc[0][0] += a.x * b.x; acc[0][1] += a.x * b.y; acc[0][2] += a.x * b.z; acc[0][3] += a.x * b.w;
            acc[1][0] += a.y * b.x; acc[1][1] += a.y * b.y; acc[1][2] += a.y * b.z; acc[1][3] += a.y * b.w;
            acc[2][0] += a.z * b.x; acc[2][1] += a.z * b.y; acc[2][2] += a.z * b.z; acc[2][3] += a.z * b.w;
            acc[3][0] += a.w * b.x; acc[3][1] += a.w * b.y; acc[3][2] += a.w * b.z; acc[3][3] += a.w * b.w;
        }
        __syncthreads();
    }
#pragma unroll
    for (int t = 0; t < 4; t++)
#pragma unroll
        for (int u = 0; u < 4; u++) {
            int m = m0 + tm * 4 + t, n = n0 + tn * 4 + u;
            g_C[(size_t)m * CW + n] = acc[t][u];
            if (n >= 1024 && n < 1056)
                g_wJ[(size_t)m * NH + (n - 1024)] = acc[t][u];
        }
}

// ---------------- qk+mask kernel: writes g_qkm[b,i][h][j] ----------------
__global__ __launch_bounds__(512) void qk_kernel(const float* __restrict__ mask)
{
    __shared__ float qs[128 * ND];
    int ic = blockIdx.x, h = blockIdx.y, b = blockIdx.z;
    int tid = threadIdx.x;
    int j = tid;
    int i0 = ic * 128;

    {
        int i = tid >> 2, d4 = tid & 3;
        float4 v = *(const float4*)&g_C[(size_t)(b * NN + i0 + i) * CW + h * ND + d4 * 4];
        *(float4*)&qs[i * ND + d4 * 4] = v;
    }
    const float* kr = g_C + (size_t)(b * NN + j) * CW + 512 + h * ND;
    float4 k0 = *(const float4*)(kr + 0);
    float4 k1 = *(const float4*)(kr + 4);
    float4 k2 = *(const float4*)(kr + 8);
    float4 k3 = *(const float4*)(kr + 12);
    __syncthreads();

    const float* mrow = mask + (((size_t)(b * NH + h) * NN + i0)) * NN + j;
    float* orow = g_qkm + ((size_t)(b * NN + i0) * NH + h) * NN + j;
#pragma unroll 1
    for (int ii = 0; ii < 128; ii += 8) {
        float mk[8];
#pragma unroll
        for (int t = 0; t < 8; t++) mk[t] = mrow[(size_t)(ii + t) * NN];
        float dv[8];
#pragma unroll
        for (int t = 0; t < 8; t++) {
            const float* q = &qs[(ii + t) * ND];
            float4 q0 = *(const float4*)(q + 0);
            float4 q1 = *(const float4*)(q + 4);
            float4 q2 = *(const float4*)(q + 8);
            float4 q3 = *(const float4*)(q + 12);
            dv[t] =
                q0.x * k0.x + q0.y * k0.y + q0.z * k0.z + q0.w * k0.w +
                q1.x * k1.x + q1.y * k1.y + q1.z * k1.z + q1.w * k1.w +
                q2.x * k2.x + q2.y * k2.y + q2.z * k2.z + q2.w * k2.w +
                q3.x * k3.x + q3.y * k3.y + q3.z * k3.z + q3.w * k3.w;
        }
#pragma unroll
        for (int t = 0; t < 8; t++)
            orow[(size_t)(ii + t) * NH * NN] = dv[t] + mk[t];
    }
}

// ---------------- fused attention kernel v14b: conflict-free GEMM rows (g + 4t), FIXED stride ----------------
// Warp = 4 g x 8 hg. Warp stages its own 32-row pair window; stats 1 row/lane.
// Thread owns rows {g + 4t}: concurrent GEMM LDS rows 1 apart -> banks 4 apart -> 1 phase.
// smem floats: pair [128][132]=16896 | wbg2 4096 | mrg 4*32*5=640 => 21632 (86.5 KB)
#define WBG_BASE  16896
#define MRG_BASE  (16896 + 4096)
#define SM_FLOATS (16896 + 4096 + 640)

__global__ __launch_bounds__(128, 2) void fused_attn_kernel(
    const float* __restrict__ pair, const float* __restrict__ dpos,
    float* __restrict__ out)
{
    extern __shared__ float sm[];
    float* pair_s = sm;

    int bi = blockIdx.x;                       // b*512 + i
    int b = bi >> 9;
    int tid = threadIdx.x;
    int lane = tid & 31, w = tid >> 5;         // 4 warps
    int hg = tid & 7, hg4 = hg * 4;
    int g = lane >> 3;                         // 0..3, thread rows = w*32 + g + 4t

    // one-time: wbg to smem, per-head constants to regs
    for (int t = tid; t < 1024; t += 128)
        ((float4*)(sm + WBG_BASE))[t] = ((const float4*)g_wbg2)[t];
    float4 c1v = *(const float4*)&g_c1[hg4];
    float4 c2v = *(const float4*)&g_c2[hg4];
    float c1a[4] = { c1v.x, c1v.y, c1v.z, c1v.w };
    float c2a[4] = { c2v.x, c2v.y, c2v.z, c2v.w };
    __syncthreads();

    const float* pbase = pair + (size_t)bi * NN * NP;
    const float* lbase = g_qkm + (size_t)bi * NH * NN;
    const unsigned long long* wb = (const unsigned long long*)(sm + WBG_BASE);

    // flash state per owned head u
    float m_r[4] = { -1e30f, -1e30f, -1e30f, -1e30f };
    float z_r[4] = { 0.f, 0.f, 0.f, 0.f };
    float a0_r[4] = {}, a1_r[4] = {}, a2_r[4] = {};

    for (int tile = 0; tile < NTILE; ++tile) {
        int j0 = tile * JT;

        // ---- warp-private staging: 32 rows (w*32 .. w*32+31), coalesced ----
        {
            const float* psrc = pbase + (size_t)(j0 + w * 32) * NP + lane * 4;
#pragma unroll
            for (int batch = 0; batch < 4; ++batch) {
                float4 ld[8];
#pragma unroll
                for (int it = 0; it < 8; ++it)
                    ld[it] = *(const float4*)(psrc + (size_t)(batch * 8 + it) * NP);
#pragma unroll
                for (int it = 0; it < 8; ++it)
                    *(float4*)&pair_s[(w * 32 + batch * 8 + it) * 132 + lane * 4] = ld[it];
            }
        }
        __syncwarp();

        // ---- LN stats: one row per lane (row w*32 + lane) ----
        float muv[8], rsv[8];
        {
            const float* pr = &pair_s[(w * 32 + lane) * 132];
            float s = 0.f, ss = 0.f;
#pragma unroll
            for (int k = 0; k < 32; k++) {
                float4 v = *(const float4*)(pr + k * 4);
                s  += v.x + v.y + v.z + v.w;
                ss += v.x * v.x + v.y * v.y + v.z * v.z + v.w * v.w;
            }
            float mu = s * (1.f / 128.f);
            float var = ss * (1.f / 128.f) - mu * mu;
            float rsd = rsqrtf(var + 1e-5f);
            // thread's rows = g + 4t; stats for local row r live on lane r
#pragma unroll
            for (int t = 0; t < 8; t++) {
                muv[t] = __shfl_sync(0xffffffffu, mu,  g + 4 * t);
                rsv[t] = __shfl_sync(0xffffffffu, rsd, g + 4 * t);
            }
        }

        // ---- bias GEMM in f32x2: 8j x 4h, K=128 as 32 p4-chunks; rows g+4t ----
        unsigned long long acc2[8][4] = {};
        const ulonglong2* pab = (const ulonglong2*)&pair_s[(w * 32 + g) * 132];
        // 4-row stride = 4*132 floats = 528 floats = 132 ulonglong2
#pragma unroll 4
        for (int p4 = 0; p4 < 32; ++p4) {
            ulonglong2 a[8];
#pragma unroll
            for (int t = 0; t < 8; t++) a[t] = pab[t * 132 + p4];
            int p2 = p4 * 2;
            ulonglong2 wA0 = *(const ulonglong2*)&wb[(size_t)(p2 + 0) * 32 + hg4];
            ulonglong2 wB0 = *(const ulonglong2*)&wb[(size_t)(p2 + 0) * 32 + hg4 + 2];
            ulonglong2 wA1 = *(const ulonglong2*)&wb[(size_t)(p2 + 1) * 32 + hg4];
            ulonglong2 wB1 = *(const ulonglong2*)&wb[(size_t)(p2 + 1) * 32 + hg4 + 2];
#pragma unroll
            for (int t = 0; t < 8; t++) {
                ffma2(acc2[t][0], a[t].x, wA0.x); ffma2(acc2[t][1], a[t].x, wA0.y);
                ffma2(acc2[t][2], a[t].x, wB0.x); ffma2(acc2[t][3], a[t].x, wB0.y);
                ffma2(acc2[t][0], a[t].y, wA1.x); ffma2(acc2[t][1], a[t].y, wA1.y);
                ffma2(acc2[t][2], a[t].y, wB1.x); ffma2(acc2[t][3], a[t].y, wB1.y);
            }
        }

        // ---- epilogue: qkm scalar (16B/4-lane groups), w j-major, dpos; online softmax ----
        float qk[4][8];
#pragma unroll
        for (int u = 0; u < 4; u++) {
            const float* qr = lbase + (size_t)(hg4 + u) * NN + j0 + w * 32 + g;
#pragma unroll
            for (int t = 0; t < 8; t++) qk[u][t] = qr[4 * t];
        }
#pragma unroll
        for (int t = 0; t < 8; t++) {
            int j = j0 + w * 32 + g + 4 * t;
            float4 w4 = *(const float4*)(g_wJ + (size_t)(b * NN + j) * NH + hg4);
            const float* dp = dpos + ((size_t)bi * NN + j) * 3;
            float dp0 = dp[0], dp1 = dp[1], dp2 = dp[2];
            float accf[4];
            float lo, hi;
            unpack2(lo, hi, acc2[t][0]); accf[0] = lo + hi;
            unpack2(lo, hi, acc2[t][1]); accf[1] = lo + hi;
            unpack2(lo, hi, acc2[t][2]); accf[2] = lo + hi;
            unpack2(lo, hi, acc2[t][3]); accf[3] = lo + hi;
            float wr[4] = { w4.x, w4.y, w4.z, w4.w };
#pragma unroll
            for (int u = 0; u < 4; u++) {
                float lv = rsv[t] * (accf[u] - muv[t] * c1a[u]) + c2a[u] + qk[u][t];
                float nm = fmaxf(m_r[u], lv);
                float sc = __expf(m_r[u] - nm);
                float e  = __expf(lv - nm);
                m_r[u] = nm;
                z_r[u] = z_r[u] * sc + e;
                float ew = e * wr[u];
                a0_r[u] = a0_r[u] * sc + ew * dp0;
                a1_r[u] = a1_r[u] * sc + ew * dp1;
                a2_r[u] = a2_r[u] * sc + ew * dp2;
            }
        }
        __syncwarp();   // next tile staging must not overwrite rows still being read
    }

    // ---- flash merge: shfl over 4 g sharing hg (xor 8,16), then across 4 warps ----
#pragma unroll
    for (int u = 0; u < 4; u++) {
#pragma unroll
        for (int off = 8; off <= 16; off <<= 1) {
            float om = __shfl_xor_sync(0xffffffffu, m_r[u], off);
            float oz = __shfl_xor_sync(0xffffffffu, z_r[u], off);
            float o0 = __shfl_xor_sync(0xffffffffu, a0_r[u], off);
            float o1 = __shfl_xor_sync(0xffffffffu, a1_r[u], off);
            float o2 = __shfl_xor_sync(0xffffffffu, a2_r[u], off);
            float M = fmaxf(m_r[u], om);
            float s1 = __expf(m_r[u] - M);
            float s2 = __expf(om - M);
            z_r[u]  = z_r[u]  * s1 + oz * s2;
            a0_r[u] = a0_r[u] * s1 + o0 * s2;
            a1_r[u] = a1_r[u] * s1 + o1 * s2;
            a2_r[u] = a2_r[u] * s1 + o2 * s2;
            m_r[u] = M;
        }
    }
    __syncthreads();
    float* mrg = sm + MRG_BASE;
    if (lane < 8) {
#pragma unroll
        for (int u = 0; u < 4; u++) {
            int h = lane * 4 + u;
            float* e = &mrg[(w * 32 + h) * 5];
            e[0] = m_r[u]; e[1] = z_r[u]; e[2] = a0_r[u]; e[3] = a1_r[u]; e[4] = a2_r[u];
        }
    }
    __syncthreads();
    if (tid < 32) {
        int h = tid;
        float M = -1e30f, Z = 0.f, A0 = 0.f, A1 = 0.f, A2 = 0.f;
#pragma unroll
        for (int ww = 0; ww < 4; ww++) {
            const float* e = &mrg[(ww * 32 + h) * 5];
            float om = e[0];
            float nM = fmaxf(M, om);
            float s1 = __expf(M - nM);
            float s2 = __expf(om - nM);
            Z  = Z * s1 + e[1] * s2;
            A0 = A0 * s1 + e[2] * s2;
            A1 = A1 * s1 + e[3] * s2;
            A2 = A2 * s1 + e[4] * s2;
            M = nM;
        }
        float inv = 1.f / Z;
        float f0 = A0 * inv, f1 = A1 * inv, f2 = A2 * inv;
#pragma unroll
        for (int o = 16; o; o >>= 1) {
            f0 += __shfl_xor_sync(0xffffffffu, f0, o);
            f1 += __shfl_xor_sync(0xffffffffu, f1, o);
            f2 += __shfl_xor_sync(0xffffffffu, f2, o);
        }
        if (tid == 0) {
            out[(size_t)bi * 3 + 0] = f0;
            out[(size_t)bi * 3 + 1] = f1;
            out[(size_t)bi * 3 + 2] = f2;
        }
    }
}

// ---------------- launcher ----------------
extern "C" void kernel_launch(void* const* d_in, const int* in_sizes, int n_in,
                              void* d_out, int out_size)
{
    (void)in_sizes; (void)n_in; (void)out_size;
    const float* query  = (const float*)d_in[0];
    const float* pair   = (const float*)d_in[1];
    const float* mask   = (const float*)d_in[2];
    const float* dpos   = (const float*)d_in[3];
    const float* ln_g   = (const float*)d_in[4];
    const float* ln_b   = (const float*)d_in[5];
    const float* Wq     = (const float*)d_in[6];
    const float* Wk     = (const float*)d_in[7];
    const float* Wv     = (const float*)d_in[8];
    const float* pln_g  = (const float*)d_in[9];
    const float* pln_b  = (const float*)d_in[10];
    const float* Wb     = (const float*)d_in[11];
    const float* bb     = (const float*)d_in[12];
    const float* Wf     = (const float*)d_in[13];
    float* out = (float*)d_out;

    static_assert(SM_FLOATS * 4 <= 113 * 1024, "smem budget for 2 CTAs/SM");
    cudaFuncSetAttribute(fused_attn_kernel,
                         cudaFuncAttributeMaxDynamicSharedMemorySize, SM_FLOATS * 4);

    prep_ln_kernel<<<1090 + NB * NN, 256>>>(Wq, Wk, Wv, Wf, Wb, bb, pln_g, pln_b,
                                            query, ln_g, ln_b);
    gemm_qkw_kernel<<<dim3(32, 17), 256>>>();
    qk_kernel<<<dim3(4, NH, NB), 512>>>(mask);
    fused_attn_kernel<<<NB * NN, 128, SM_FLOATS * 4>>>(pair, dpos, out);
}